// round 15
// baseline (speedup 1.0000x reference)
#include <cuda_runtime.h>

// Problem constants (fixed by reference_code)
#define Bc 2
#define Nc 65536
#define Hc 128
#define Wc 128
#define HWc 16384
#define TDX 16                 // tile width
#define TDY 8                  // tile height
#define NTLX 8                 // x tiles
#define NTLY 16                // y tiles
#define NTILE 128              // tiles per camera
#define NBT (Bc * NTILE)       // 256 (camera, tile) pairs
#define NCHUNK 256             // 256-gaussian chunks per camera
#define SEG 256                // list entries per splat work item
#define KC 32                  // staged chunk in splat
#define NTHR 32                // splat block size
// cutoff: include iff a*dist2 >= -10 (e^-10 ~ 4.5e-5 weight). Measured:
// -20.8 -> -14 moved rel_err by 8e-9; dropped mass ~ e^c => -10 adds ~4e-7.
#define CULL_LN (-10.0f)
#define LISTCAP (Bc * Nc * 16 + 64)  // r<=13.5 -> <=3x5=15 tiles/gaussian
#define MAXITEMS 8704                // >= LISTCAP/SEG + NBT

// Scratch (static __device__ arrays — no allocation at runtime)
__device__ float4 g_params[Bc * Nc];            // proj_x, proj_y, a=-0.5/var, op
__device__ float4 g_colop[Nc];                  // (op*cr, op*cg, op*cb, op)
__device__ ulonglong2 g_mask[Bc * Nc];          // 128-bit tile cover mask
__device__ unsigned int g_cnt[NBT * NCHUNK];    // per (b,tile,chunk) counts
__device__ unsigned int g_off[NBT * NCHUNK];    // exclusive prefix within (b,tile)
__device__ int g_tilebase[NBT + 1];             // list base per (b,tile)
__device__ int g_itembase[NBT + 1];             // item base per (b,tile)
__device__ int g_nitems;
__device__ unsigned int g_items[MAXITEMS];      // b<<24 | tile<<16 | seg
__device__ unsigned short g_list[LISTCAP];      // gaussian index within camera
__device__ float g_part[(size_t)MAXITEMS * 512]; // per-item partials [4ch][128px]

// ---------------------------------------------------------------------------
// Kernel 1: projection params + colop fold + 128-bit tile mask + counts.
//   grid = 512 blocks (b = blk>>8, chunk c = blk&255), 256 threads.
// ---------------------------------------------------------------------------
__global__ void __launch_bounds__(256) k_params(
        const float* __restrict__ pos,
        const float* __restrict__ colors,
        const float* __restrict__ opa,
        const float* __restrict__ scl,
        const float* __restrict__ qv,
        const float* __restrict__ tv,
        const float* __restrict__ fx_,
        const float* __restrict__ fy_,
        const float* __restrict__ cx_,
        const float* __restrict__ cy_) {
    __shared__ unsigned int scnt[NTILE];

    const int t = threadIdx.x;
    const int b = blockIdx.x >> 8;
    const int c = blockIdx.x & 255;
    const int n = c * 256 + t;
    const int idx = b * Nc + n;

    if (t < NTILE) scnt[t] = 0u;
    __syncthreads();

    float qw = qv[b * 4 + 0], qx = qv[b * 4 + 1], qy = qv[b * 4 + 2], qz = qv[b * 4 + 3];
    float inv = rsqrtf(qw * qw + qx * qx + qy * qy + qz * qz);
    qw *= inv; qx *= inv; qy *= inv; qz *= inv;

    float R00 = 1.f - 2.f * (qy * qy + qz * qz);
    float R01 = 2.f * (qx * qy - qz * qw);
    float R02 = 2.f * (qx * qz + qy * qw);
    float R10 = 2.f * (qx * qy + qz * qw);
    float R11 = 1.f - 2.f * (qx * qx + qz * qz);
    float R12 = 2.f * (qy * qz - qx * qw);
    float R20 = 2.f * (qx * qz - qy * qw);
    float R21 = 2.f * (qy * qz + qx * qw);
    float R22 = 1.f - 2.f * (qx * qx + qy * qy);

    float px = pos[3 * n], py = pos[3 * n + 1], pz = pos[3 * n + 2];
    float cxm = R00 * px + R01 * py + R02 * pz + tv[b * 3 + 0];
    float cym = R10 * px + R11 * py + R12 * pz + tv[b * 3 + 1];
    float czm = R20 * px + R21 * py + R22 * pz + tv[b * 3 + 2];

    float projx = cxm / czm * fx_[0] + cx_[0];
    float projy = cym / czm * fy_[0] + cy_[0];
    float op = opa[n];
    float s = scl[n];
    float a = -0.5f / (s * s);

    g_params[idx] = make_float4(projx, projy, a, op);
    if (b == 0) {
        g_colop[n] = make_float4(op * colors[3 * n], op * colors[3 * n + 1],
                                 op * colors[3 * n + 2], op);
    }

    // 128-bit tile cover mask (exact clamped-corner test)
    unsigned long long mlo = 0ull, mhi = 0ull;
    float r = sqrtf(CULL_LN / a);              // sqrt(20*var)
    int txlo = (int)fmaxf(0.f, fminf(7.f,  floorf((projx - r) * 0.0625f)));
    int txhi = (int)fmaxf(0.f, fminf(7.f,  floorf((projx + r) * 0.0625f)));
    int tylo = (int)fmaxf(0.f, fminf(15.f, floorf((projy - r) * 0.125f)));
    int tyhi = (int)fmaxf(0.f, fminf(15.f, floorf((projy + r) * 0.125f)));
    for (int ty = tylo; ty <= tyhi; ty++) {
        float ylo = (float)(ty * TDY), yhi = ylo + (float)(TDY - 1);
        float ey = fmaxf(fmaxf(ylo - projy, projy - yhi), 0.f);
        for (int tx = txlo; tx <= txhi; tx++) {
            float xlo = (float)(tx * TDX), xhi = xlo + (float)(TDX - 1);
            float ex = fmaxf(fmaxf(xlo - projx, projx - xhi), 0.f);
            if (a * (ex * ex + ey * ey) >= CULL_LN) {
                int tl = ty * NTLX + tx;
                if (tl < 64) mlo |= 1ull << tl;
                else         mhi |= 1ull << (tl - 64);
            }
        }
    }
    g_mask[idx] = make_ulonglong2(mlo, mhi);

    // per-tile counts: smem atomics (order-independent => exact counts)
    unsigned long long mm = mlo;
    while (mm) { int tl = __ffsll((long long)mm) - 1; mm &= mm - 1; atomicAdd(&scnt[tl], 1u); }
    mm = mhi;
    while (mm) { int tl = __ffsll((long long)mm) - 1; mm &= mm - 1; atomicAdd(&scnt[tl + 64], 1u); }
    __syncthreads();
    if (t < NTILE) g_cnt[(b * NTILE + t) * NCHUNK + c] = scnt[t];
}

// ---------------------------------------------------------------------------
// Kernel 2: scan — per-bt chunk prefix (64-wide batches), dual Hillis-Steele
//   prefix over 256 bt, item table. Single block, 256 threads (one bt each).
// ---------------------------------------------------------------------------
__global__ void __launch_bounds__(256) k_scan() {
    __shared__ int ssl[NBT];
    __shared__ int sns[NBT];
    const int t = threadIdx.x;   // bt index

    unsigned run = 0;
    const int base = t * NCHUNK;
    for (int c0 = 0; c0 < NCHUNK; c0 += 64) {
        unsigned v[64];
#pragma unroll
        for (int i = 0; i < 64; i++) v[i] = g_cnt[base + c0 + i];   // MLP=64
#pragma unroll
        for (int i = 0; i < 64; i++) { g_off[base + c0 + i] = run; run += v[i]; }
    }
    const int slen = (int)run;
    const int ns = (slen + SEG - 1) >> 8;

    ssl[t] = slen; sns[t] = ns;
    __syncthreads();
    // inclusive Hillis-Steele scan over 256
    for (int off = 1; off < NBT; off <<= 1) {
        int vs = 0, vn = 0;
        if (t >= off) { vs = ssl[t - off]; vn = sns[t - off]; }
        __syncthreads();
        ssl[t] += vs; sns[t] += vn;
        __syncthreads();
    }
    const int tb = ssl[t] - slen;     // exclusive
    const int ib = sns[t] - ns;
    g_tilebase[t] = tb;
    g_itembase[t] = ib;
    if (t == NBT - 1) {
        g_tilebase[NBT] = ssl[t];
        g_itembase[NBT] = sns[t];
        g_nitems = sns[t];
    }
    const unsigned hdr = ((unsigned)(t >> 7) << 24) | ((unsigned)(t & 127) << 16);
    for (int s2 = 0; s2 < ns; s2++)
        g_items[ib + s2] = hdr | (unsigned)s2;
}

// ---------------------------------------------------------------------------
// Kernel 3: scatter gaussian indices into per-tile lists (index-ordered,
//   deterministic). Warp-prefix table -> O(1) rank per entry.
//   grid = 512 blocks (b, chunk), 256 threads.
// ---------------------------------------------------------------------------
__global__ void __launch_bounds__(256) k_scatter() {
    __shared__ unsigned int bals[8][NTILE];       // 4 KB
    __shared__ unsigned short spre[8][NTILE];     // 2 KB

    const int t = threadIdx.x;
    const int b = blockIdx.x >> 8;
    const int c = blockIdx.x & 255;
    const int n = c * 256 + t;
    const ulonglong2 mk = g_mask[b * Nc + n];
    const int wid = t >> 5, lane = t & 31;

    for (int tl = 0; tl < 64; tl++) {
        unsigned bal = __ballot_sync(0xffffffffu, (mk.x >> tl) & 1ull);
        if (lane == 0) bals[wid][tl] = bal;
    }
    for (int tl = 0; tl < 64; tl++) {
        unsigned bal = __ballot_sync(0xffffffffu, (mk.y >> tl) & 1ull);
        if (lane == 0) bals[wid][tl + 64] = bal;
    }
    __syncthreads();

    // exclusive warp-prefix per tile
#pragma unroll
    for (int s2 = t; s2 < 8 * NTILE; s2 += 256) {
        int tl = s2 >> 3, w = s2 & 7;
        int sum = 0;
        for (int w2 = 0; w2 < w; w2++) sum += __popc(bals[w2][tl]);
        spre[w][tl] = (unsigned short)sum;
    }
    __syncthreads();

    const unsigned lanemask = (1u << lane) - 1u;
    unsigned long long mm = mk.x;
    while (mm) {
        int tl = __ffsll((long long)mm) - 1;
        mm &= mm - 1;
        int rank = (int)spre[wid][tl] + __popc(bals[wid][tl] & lanemask);
        int bt = b * NTILE + tl;
        g_list[g_tilebase[bt] + (int)g_off[bt * NCHUNK + c] + rank] = (unsigned short)n;
    }
    mm = mk.y;
    while (mm) {
        int tl = __ffsll((long long)mm) - 1 + 64;
        mm &= mm - 1;
        int rank = (int)spre[wid][tl] + __popc(bals[wid][tl] & lanemask);
        int bt = b * NTILE + tl;
        g_list[g_tilebase[bt] + (int)g_off[bt * NCHUNK + c] + rank] = (unsigned short)n;
    }
}

// ---------------------------------------------------------------------------
// Kernel 4: splat — one 256-entry list segment per 32-thread block.
//   Tile 16x8; micro-tile 4x*1y*4ch: inner = 2x LDS.128 + 16 FFMA per k.
//   grid = MAXITEMS blocks (early exit past g_nitems).
// ---------------------------------------------------------------------------
__global__ void __launch_bounds__(NTHR) k_splat() {
    __shared__ float  us[KC][TDX];          // 2 KB
    __shared__ float4 ds[KC][TDY];          // 4 KB
    __shared__ unsigned short lst[SEG];     // 0.5 KB

    const int item = blockIdx.x;
    if (item >= g_nitems) return;
    const unsigned rec = g_items[item];
    const int b = rec >> 24, tile = (rec >> 16) & 0xff, seg = rec & 0xffff;
    const int bt = b * NTILE + tile;
    const int base = g_tilebase[bt];
    const int len = g_tilebase[bt + 1] - base;
    const int start = seg * SEG;
    const int m = min(SEG, len - start);
    const int t = threadIdx.x;

    // preload list slice (scalar u16 loads — base may be odd)
#pragma unroll
    for (int i = 0; i < SEG / NTHR; i++)
        if (t + i * NTHR < m) lst[t + i * NTHR] = g_list[base + start + t + i * NTHR];

    const float4* __restrict__ prm = &g_params[b * Nc];
    const int x0 = (tile & 7) * TDX, y0 = (tile >> 3) * TDY;
    const int tx = t & 3, ty = t >> 2;      // 4x * 1y micro-tile (ty 0..7)
    const int xu = t & 15, kU = t >> 4;     // u-stage: k = kU + 2i, 16 slots
    const int yv = t & 7,  kD = t >> 3;     // d-stage: k = kD + 4i, 8 slots

    float acc[4][4];
#pragma unroll
    for (int xi = 0; xi < 4; xi++)
#pragma unroll
        for (int ch = 0; ch < 4; ch++) acc[xi][ch] = 0.f;

    __syncwarp();   // lst visible (single warp)

    for (int kb = 0; kb < m; kb += KC) {
        // ---- stage u: 32k x 16x
#pragma unroll
        for (int i = 0; i < 16; i++) {
            int k = kU + i * 2;
            int kk = kb + k;
            float u = 0.f;
            if (kk < m) {
                int n = (int)lst[kk];
                float4 pr = prm[n];
                float dx = (float)(x0 + xu) - pr.x;
                u = __expf(pr.z * dx * dx);
            }
            us[k][xu] = u;
        }
        // ---- stage d: 32k x 8y (folded colors)
#pragma unroll
        for (int i = 0; i < 8; i++) {
            int k = kD + i * 4;
            int kk = kb + k;
            float4 dval = make_float4(0.f, 0.f, 0.f, 0.f);
            if (kk < m) {
                int n = (int)lst[kk];
                float4 pr = prm[n];
                float4 co = g_colop[n];
                float dy = (float)(y0 + yv) - pr.y;
                float e = __expf(pr.z * dy * dy);
                dval = make_float4(co.x * e, co.y * e, co.z * e, co.w * e);
            }
            ds[k][yv] = dval;
        }
        __syncwarp();

        // ---- inner: 16 FFMA + 2x LDS.128 per k per thread
#pragma unroll 16
        for (int k = 0; k < KC; k++) {
            float4 u4 = *reinterpret_cast<const float4*>(&us[k][tx * 4]);
            float4 d  = ds[k][ty];
            acc[0][0] += u4.x * d.x; acc[0][1] += u4.x * d.y;
            acc[0][2] += u4.x * d.z; acc[0][3] += u4.x * d.w;
            acc[1][0] += u4.y * d.x; acc[1][1] += u4.y * d.y;
            acc[1][2] += u4.y * d.z; acc[1][3] += u4.y * d.w;
            acc[2][0] += u4.z * d.x; acc[2][1] += u4.z * d.y;
            acc[2][2] += u4.z * d.z; acc[2][3] += u4.z * d.w;
            acc[3][0] += u4.w * d.x; acc[3][1] += u4.w * d.y;
            acc[3][2] += u4.w * d.z; acc[3][3] += u4.w * d.w;
        }
        __syncwarp();
    }

    // ---- write per-item partial [4ch][128px] (p = 4t, contiguous per warp)
    float* pb = &g_part[(size_t)item * 512];
    const int p = ty * TDX + tx * 4;
#pragma unroll
    for (int ch = 0; ch < 4; ch++)
        *reinterpret_cast<float4*>(&pb[ch * 128 + p]) =
            make_float4(acc[0][ch], acc[1][ch], acc[2][ch], acc[3][ch]);
}

// ---------------------------------------------------------------------------
// Kernel 5: finalize — per-(b,tile) block (128 threads, one pixel each)
//   sums its segments, adds 32*EPS, divides, writes (B,3,H,W).
// ---------------------------------------------------------------------------
__global__ void __launch_bounds__(128) k_finalize(float* __restrict__ out) {
    const int bt = blockIdx.x;
    const int b = bt >> 7, tile = bt & 127;
    const int p = threadIdx.x;   // 0..127
    const int itb = g_itembase[bt];
    const int ns = g_itembase[bt + 1] - itb;

    float r = 0.f, gg = 0.f, bb = 0.f;
    float d = 32.0f * 1e-8f;   // n_chunks(=32 of 2048) * EPS from reference scan
    for (int s = 0; s < ns; s++) {
        const float* pb = &g_part[(size_t)(itb + s) * 512];
        r  += pb[p];
        gg += pb[128 + p];
        bb += pb[256 + p];
        d  += pb[384 + p];
    }
    float inv = 1.0f / fmaxf(d, 1e-8f);
    const int col = p & 15, row = p >> 4;
    const int gp = ((tile >> 3) * TDY + row) * Wc + (tile & 7) * TDX + col;
    out[(b * 3 + 0) * HWc + gp] = r  * inv;
    out[(b * 3 + 1) * HWc + gp] = gg * inv;
    out[(b * 3 + 2) * HWc + gp] = bb * inv;
}

// ---------------------------------------------------------------------------
extern "C" void kernel_launch(void* const* d_in, const int* in_sizes, int n_in,
                              void* d_out, int out_size) {
    const float* pos = (const float*)d_in[0];
    const float* col = (const float*)d_in[1];
    const float* opa = (const float*)d_in[2];
    const float* scl = (const float*)d_in[3];
    const float* qv  = (const float*)d_in[4];
    const float* tv  = (const float*)d_in[5];
    const float* fx  = (const float*)d_in[6];
    const float* fy  = (const float*)d_in[7];
    const float* cx  = (const float*)d_in[8];
    const float* cy  = (const float*)d_in[9];

    k_params<<<(Bc * Nc) / 256, 256>>>(pos, col, opa, scl, qv, tv, fx, fy, cx, cy);
    k_scan<<<1, 256>>>();
    k_scatter<<<(Bc * Nc) / 256, 256>>>();
    k_splat<<<MAXITEMS, NTHR>>>();
    k_finalize<<<NBT, 128>>>((float*)d_out);
}

// round 16
// speedup vs baseline: 1.8989x; 1.8989x over previous
#include <cuda_runtime.h>

// Problem constants (fixed by reference_code)
#define Bc 2
#define Nc 65536
#define Hc 128
#define Wc 128
#define HWc 16384
#define Gsplit 32              // split-K factor over gaussians
#define KN (Nc / Gsplit)       // 2048 gaussians per block range
#define KC 32                  // chunk of gaussians staged in smem
#define NTX 8
#define NTY 8
#define NTILE 64               // tiles per camera
#define TDIMX 16
#define TDIMY 16
#define NTHR 128
#define NWARP (NTHR / 32)
#define NITER (KN / NTHR)      // 16 compaction rounds (2 batches of 8)
// cutoff: op*exp(a*d^2) <= e^-14 ~ 8.3e-7; validated rel_err ~9.3e-7 (R7-R14)
#define CULL_LN (-14.0f)

// Scratch (static __device__ arrays — no allocation at runtime)
__device__ float4 g_params[Bc * Nc];            // proj_x, proj_y, a=-0.5/var, op
__device__ float4 g_colop[Nc];                  // (op*cr, op*cg, op*cb, op)
__device__ float  g_part[Bc * Gsplit * 4 * HWc];// split-K partials (r,g,b,den)
__device__ int    g_done[Bc * NTILE];           // arrival counters per (b,tile)

// ---------------------------------------------------------------------------
// Kernel 1: projection params + colop fold + reset arrival counters.
// ---------------------------------------------------------------------------
__global__ void __launch_bounds__(256) k_params(
        const float* __restrict__ pos,
        const float* __restrict__ colors,
        const float* __restrict__ opa,
        const float* __restrict__ scl,
        const float* __restrict__ qv,
        const float* __restrict__ tv,
        const float* __restrict__ fx_,
        const float* __restrict__ fy_,
        const float* __restrict__ cx_,
        const float* __restrict__ cy_) {
    int idx = blockIdx.x * blockDim.x + threadIdx.x;
    if (idx < Bc * NTILE) g_done[idx] = 0;
    if (idx >= Bc * Nc) return;
    int b = idx >> 16;            // Nc = 65536
    int n = idx & (Nc - 1);

    float qw = qv[b * 4 + 0], qx = qv[b * 4 + 1], qy = qv[b * 4 + 2], qz = qv[b * 4 + 3];
    float inv = rsqrtf(qw * qw + qx * qx + qy * qy + qz * qz);
    qw *= inv; qx *= inv; qy *= inv; qz *= inv;

    float R00 = 1.f - 2.f * (qy * qy + qz * qz);
    float R01 = 2.f * (qx * qy - qz * qw);
    float R02 = 2.f * (qx * qz + qy * qw);
    float R10 = 2.f * (qx * qy + qz * qw);
    float R11 = 1.f - 2.f * (qx * qx + qz * qz);
    float R12 = 2.f * (qy * qz - qx * qw);
    float R20 = 2.f * (qx * qz - qy * qw);
    float R21 = 2.f * (qy * qz + qx * qw);
    float R22 = 1.f - 2.f * (qx * qx + qy * qy);

    float px = pos[3 * n], py = pos[3 * n + 1], pz = pos[3 * n + 2];
    float cxm = R00 * px + R01 * py + R02 * pz + tv[b * 3 + 0];
    float cym = R10 * px + R11 * py + R12 * pz + tv[b * 3 + 1];
    float czm = R20 * px + R21 * py + R22 * pz + tv[b * 3 + 2];

    float projx = cxm / czm * fx_[0] + cx_[0];
    float projy = cym / czm * fy_[0] + cy_[0];
    float op = opa[n];
    float s = scl[n];
    float a = -0.5f / (s * s);

    g_params[idx] = make_float4(projx, projy, a, op);
    if (b == 0) {
        g_colop[n] = make_float4(op * colors[3 * n], op * colors[3 * n + 1],
                                 op * colors[3 * n + 2], op);
    }
}

// ---------------------------------------------------------------------------
// Kernel 2: culled separable splat, 16x16 tiles, 128-thread blocks.
//   grid = (32 splits, 64 tiles, 2 cams) = 4096 blocks.
//   Phase A: batched compaction (proven R9): 2 prefetch batches of 8 LDG.128,
//            ballots, one BAR + register prefix + scatter.
//   Phase B: merged staging (one lst/prm/colop load + 2 exps per slot);
//            inner: 8 FFMA + LDS.64 + LDS.128 per gaussian per thread.
//   Tail:    last block per (b,tile) reduces 32 partials in fixed order and
//            writes final pixels (fused finalize, deterministic values).
// ---------------------------------------------------------------------------
__global__ void __launch_bounds__(NTHR) k_splat(float* __restrict__ out) {
    __shared__ float  us[KC][TDIMX];        // 2 KB
    __shared__ float4 ds[KC][TDIMY];        // 8 KB
    __shared__ unsigned short list[KN];     // 4 KB
    __shared__ int cnts[NITER][NWARP];
    __shared__ int s_last;

    const int t    = threadIdx.x;
    const int g    = blockIdx.x;            // k-split index
    const int tile = blockIdx.y;            // 0..63
    const int b    = blockIdx.z;            // camera
    const int x0   = (tile & (NTX - 1)) * TDIMX;
    const int y0   = (tile / NTX) * TDIMY;
    const int kbase0 = g * KN;
    const int wid  = t >> 5, lane = t & 31;

    const float4* __restrict__ prm = &g_params[b * Nc];

    // ---------------- Phase A: batched deterministic compaction ------------
    const float xlo = (float)x0, xhi = (float)(x0 + TDIMX - 1);
    const float ylo = (float)y0, yhi = (float)(y0 + TDIMY - 1);
    unsigned msk[NITER];

#pragma unroll
    for (int batch = 0; batch < 2; batch++) {
        float4 pp[NITER / 2];
#pragma unroll
        for (int i = 0; i < NITER / 2; i++)
            pp[i] = prm[kbase0 + (batch * (NITER / 2) + i) * NTHR + t];
#pragma unroll
        for (int i = 0; i < NITER / 2; i++) {
            int ii = batch * (NITER / 2) + i;
            float ex = fmaxf(fmaxf(xlo - pp[i].x, pp[i].x - xhi), 0.0f);
            float ey = fmaxf(fmaxf(ylo - pp[i].y, pp[i].y - yhi), 0.0f);
            bool inc = pp[i].z * (ex * ex + ey * ey) >= CULL_LN;
            msk[ii] = __ballot_sync(0xffffffffu, inc);
            if (lane == 0) cnts[ii][wid] = __popc(msk[ii]);
        }
    }
    __syncthreads();

    int pre[NITER];
    int run = 0;
#pragma unroll
    for (int i = 0; i < NITER; i++) {
#pragma unroll
        for (int w = 0; w < NWARP; w++) {
            if (w == wid) pre[i] = run;
            run += cnts[i][w];
        }
    }
    const int cnt = run;

#pragma unroll
    for (int i = 0; i < NITER; i++) {
        if ((msk[i] >> lane) & 1u)
            list[pre[i] + __popc(msk[i] & ((1u << lane) - 1u))] =
                (unsigned short)(i * NTHR + t);
    }
    __syncthreads();

    // ---------------- Phase B: chunked accumulation over the list ----------
    const int tx  = t & 7;                 // px base = x0 + 2*tx
    const int tyy = t >> 3;                // py = y0 + tyy (0..15)
    const int xu  = t & 15, ku0 = t >> 4;  // staging: 4 slots (k = ku0 + 8i)

    float acc[2][4];
#pragma unroll
    for (int xi = 0; xi < 2; xi++)
#pragma unroll
        for (int ch = 0; ch < 4; ch++) acc[xi][ch] = 0.f;

    for (int kb = 0; kb < cnt; kb += KC) {
        __syncthreads();   // previous chunk consumers done

        // ---- merged staging: one lst/prm/colop load + 2 exps per slot
#pragma unroll
        for (int i = 0; i < 4; i++) {
            int k = ku0 + i * 8;
            int kk = kb + k;
            float u = 0.f;
            float4 dval = make_float4(0.f, 0.f, 0.f, 0.f);
            if (kk < cnt) {
                int n = kbase0 + (int)list[kk];
                float4 pr = prm[n];
                float4 co = g_colop[n];
                float dx = (float)(x0 + xu) - pr.x;
                float dy = (float)(y0 + xu) - pr.y;
                u = __expf(pr.z * dx * dx);
                float e = __expf(pr.z * dy * dy);
                dval = make_float4(co.x * e, co.y * e, co.z * e, co.w * e);
            }
            us[k][xu] = u;
            ds[k][xu] = dval;
        }
        __syncthreads();

        // ---- inner: 8 FFMA + LDS.64 + LDS.128 per k per thread
#pragma unroll 16
        for (int k = 0; k < KC; k++) {
            float2 u2 = *reinterpret_cast<const float2*>(&us[k][tx * 2]);
            float4 d  = ds[k][tyy];
            acc[0][0] += u2.x * d.x;
            acc[0][1] += u2.x * d.y;
            acc[0][2] += u2.x * d.z;
            acc[0][3] += u2.x * d.w;
            acc[1][0] += u2.y * d.x;
            acc[1][1] += u2.y * d.y;
            acc[1][2] += u2.y * d.z;
            acc[1][3] += u2.y * d.w;
        }
    }

    // ---- write deterministic split-K partials (4x STG.64 per thread)
    const int base_bg = ((b * Gsplit + g) * 4) * HWc;
    const int pidx = (y0 + tyy) * Wc + x0 + tx * 2;
#pragma unroll
    for (int ch = 0; ch < 4; ch++) {
        float2 o = make_float2(acc[0][ch], acc[1][ch]);
        *reinterpret_cast<float2*>(&g_part[base_bg + ch * HWc + pidx]) = o;
    }

    // ---------------- Tail: last block per (b,tile) reduces ----------------
    __threadfence();
    __syncthreads();
    if (t == 0) {
        int prev = atomicAdd(&g_done[b * NTILE + tile], 1);
        s_last = (prev == Gsplit - 1);
    }
    __syncthreads();
    if (!s_last) return;

    // reduce 32 partials in fixed split order (deterministic values).
    // thread t handles 2 pixels: local l = 2t -> (ly, lx)
    const int ly = (2 * t) >> 4, lx = (2 * t) & 15;
    const int rp = (y0 + ly) * Wc + x0 + lx;
    float2 r  = make_float2(0.f, 0.f);
    float2 gg = make_float2(0.f, 0.f);
    float2 bb = make_float2(0.f, 0.f);
    float2 dd = make_float2(32.0f * 1e-8f, 32.0f * 1e-8f);  // n_chunks*EPS
#pragma unroll 4
    for (int s = 0; s < Gsplit; s++) {
        const float* pb = &g_part[((b * Gsplit + s) * 4) * HWc + rp];
        float2 v0 = *reinterpret_cast<const float2*>(&pb[0]);
        float2 v1 = *reinterpret_cast<const float2*>(&pb[HWc]);
        float2 v2 = *reinterpret_cast<const float2*>(&pb[2 * HWc]);
        float2 v3 = *reinterpret_cast<const float2*>(&pb[3 * HWc]);
        r.x  += v0.x; r.y  += v0.y;
        gg.x += v1.x; gg.y += v1.y;
        bb.x += v2.x; bb.y += v2.y;
        dd.x += v3.x; dd.y += v3.y;
    }
    float iv0 = 1.0f / fmaxf(dd.x, 1e-8f);
    float iv1 = 1.0f / fmaxf(dd.y, 1e-8f);
    *reinterpret_cast<float2*>(&out[(b * 3 + 0) * HWc + rp]) =
        make_float2(r.x * iv0, r.y * iv1);
    *reinterpret_cast<float2*>(&out[(b * 3 + 1) * HWc + rp]) =
        make_float2(gg.x * iv0, gg.y * iv1);
    *reinterpret_cast<float2*>(&out[(b * 3 + 2) * HWc + rp]) =
        make_float2(bb.x * iv0, bb.y * iv1);
}

// ---------------------------------------------------------------------------
extern "C" void kernel_launch(void* const* d_in, const int* in_sizes, int n_in,
                              void* d_out, int out_size) {
    const float* pos = (const float*)d_in[0];
    const float* col = (const float*)d_in[1];
    const float* opa = (const float*)d_in[2];
    const float* scl = (const float*)d_in[3];
    const float* qv  = (const float*)d_in[4];
    const float* tv  = (const float*)d_in[5];
    const float* fx  = (const float*)d_in[6];
    const float* fy  = (const float*)d_in[7];
    const float* cx  = (const float*)d_in[8];
    const float* cy  = (const float*)d_in[9];

    k_params<<<(Bc * Nc) / 256, 256>>>(pos, col, opa, scl, qv, tv, fx, fy, cx, cy);

    dim3 grid(Gsplit, NTILE, Bc);   // 32 * 64 * 2 = 4096 blocks
    k_splat<<<grid, NTHR>>>((float*)d_out);
}